// round 7
// baseline (speedup 1.0000x reference)
#include <cuda_runtime.h>
#include <cuda_bf16.h>
#include <cstdint>

#define DH 384
#define DG 192
#define TT 48
#define BB 96
#define NTH 384
#define NW 12
#define LAM 0.9f
#define ETA 0.5f
#define LN_EPS 1e-5f

typedef unsigned long long ull;

// ---------------- device scratch (allocation-free rule) ----------------
__device__ float WT_g[DH * DH];              // W_h transposed: WT[j*DH + o] = W_h[o*DH + j]
__device__ float WGT_g[DG * DH];             // W_g transposed
__device__ float ZP_g[(size_t)TT * BB * DH]; // z @ W_g^T + b_h

// ---------------- helpers ----------------
__device__ __forceinline__ float wred(float v) {
#pragma unroll
    for (int o = 16; o; o >>= 1) v += __shfl_xor_sync(0xffffffffu, v, o);
    return v;
}
__device__ __forceinline__ ull fma2(ull a, ull b, ull c) {
    ull d;
    asm("fma.rn.f32x2 %0, %1, %2, %3;" : "=l"(d) : "l"(a), "l"(b), "l"(c));
    return d;
}
__device__ __forceinline__ ull pack2(float lo, float hi) {
    ull d;
    asm("mov.b64 %0, {%1, %2};" : "=l"(d) : "f"(lo), "f"(hi));
    return d;
}
__device__ __forceinline__ ull splat2(float x) {
    ull d;
    asm("mov.b64 %0, {%1, %1};" : "=l"(d) : "f"(x));
    return d;
}
__device__ __forceinline__ float2 unpack2(ull v) {
    float lo, hi;
    asm("mov.b64 {%0, %1}, %2;" : "=f"(lo), "=f"(hi) : "l"(v));
    return make_float2(lo, hi);
}

// ---------------- transpose prep ----------------
__global__ void transpose_k(const float* __restrict__ src, int rows, int cols, int which) {
    __shared__ float tile[32][33];
    float* dst = (which == 0) ? WT_g : WGT_g;
    int c0 = blockIdx.x * 32, r0 = blockIdx.y * 32;
    int tx = threadIdx.x, ty = threadIdx.y;
#pragma unroll
    for (int k = 0; k < 4; k++)
        tile[ty + 8 * k][tx] = src[(size_t)(r0 + ty + 8 * k) * cols + c0 + tx];
    __syncthreads();
#pragma unroll
    for (int k = 0; k < 4; k++)
        dst[(size_t)(c0 + ty + 8 * k) * rows + r0 + tx] = tile[tx][ty + 8 * k];
}

// ---------------- z-projection prep (f32x2) ----------------
__global__ void zp_kernel(const float* __restrict__ z, const float* __restrict__ bh) {
    __shared__ float zt[DG * 18];   // transposed: zt[i*18 + m]
    int t = blockIdx.x / 6, bc = blockIdx.x % 6;
    int j = threadIdx.x;
    const float* zsrc = z + ((size_t)t * BB + bc * 16) * DG;
    for (int idx = j; idx < 16 * DG; idx += NTH) {
        int m = idx / DG, i = idx % DG;
        zt[i * 18 + m] = zsrc[idx];
    }
    __syncthreads();
    ull acc[8];
    ull b2 = splat2(bh[j]);
#pragma unroll
    for (int p = 0; p < 8; p++) acc[p] = b2;
    for (int i = 0; i < DG; i++) {
        ull ws = splat2(WGT_g[(size_t)i * DH + j]);
        const ull* z2 = (const ull*)(zt + i * 18);
#pragma unroll
        for (int p = 0; p < 8; p++) acc[p] = fma2(ws, z2[p], acc[p]);
    }
    float* dst = ZP_g + ((size_t)t * BB + bc * 16) * DH + j;
#pragma unroll
    for (int p = 0; p < 8; p++) {
        float2 f = unpack2(acc[p]);
        dst[(size_t)(2 * p + 0) * DH] = f.x;
        dst[(size_t)(2 * p + 1) * DH] = f.y;
    }
}

// ---------------- main recurrence: one CTA per 2 batches ----------------
// dynamic smem (ull): histP 47*384 | hsP 384 | part 4*384 | dotsP 48
// then floats: lampow 48 | red 4*12 | p5 10*12
#define SM_ULL (47 * DH + DH + 4 * DH + 48)
#define SM_BYTES (SM_ULL * 8 + (48 + 48 + 120) * 4)

__global__ void __launch_bounds__(NTH, 1)
rnn_kernel(const float* __restrict__ lng, const float* __restrict__ lnb,
           const float* __restrict__ alpha, float* __restrict__ out) {
    extern __shared__ __align__(16) ull sm_u[];
    ull* histP   = sm_u;                   // packed (b0,b1) history
    ull* hsP     = histP + 47 * DH;        // packed current h
    ull* part    = hsP + DH;               // packed gemv partials
    ull* dotsP   = part + 4 * DH;          // packed dot coefficients
    float* lampow = (float*)(dotsP + 48);  // 48
    float* red    = lampow + 48;           // 4 rows x 12
    float* p5     = red + 48;              // 10 rows x 12

    const int b0 = blockIdx.x * 2, b1 = b0 + 1;
    const int tid = threadIdx.x;
    const int w = tid >> 5, l = tid & 31;
    const int q = tid / 96, c = tid % 96;

    float alf = alpha[0];
    float kexp = (alf >= 0.f) ? (1.f + log1pf(expf(alf)))
                              : (1.f / (1.f + log1pf(expf(-alf))));
    float gj = lng[tid], bj = lnb[tid];

    if (tid < 48) lampow[tid] = ETA * powf(LAM, (float)tid);
    hsP[tid] = 0ull;
    __syncthreads();

    const float4* WT4 = (const float4*)WT_g;
    float hc0 = 0.f, hc1 = 0.f;

    for (int t = 0; t < TT; t++) {
        // ---------- gemv: hb = W_h @ hs + ZP, both batches share W loads ----------
        float zp0 = ZP_g[((size_t)t * BB + b0) * DH + tid];
        float zp1 = ZP_g[((size_t)t * BB + b1) * DH + tid];
        float A00 = 0.f, A01 = 0.f, A02 = 0.f, A03 = 0.f;
        float B00 = 0.f, B01 = 0.f, B02 = 0.f, B03 = 0.f;
        const ull* hrow = hsP + q * 96;
        const float4* wbase = WT4 + (size_t)(q * 96) * 96 + c;
#pragma unroll 2
        for (int j = 0; j < 96; j += 2) {
            ulonglong2 hp = *(const ulonglong2*)(hrow + j);
            float2 ha = unpack2(hp.x);
            float2 hbq = unpack2(hp.y);
            float4 w0 = wbase[(size_t)j * 96];
            float4 w1 = wbase[(size_t)(j + 1) * 96];
            A00 = fmaf(w0.x, ha.x, A00);  B00 = fmaf(w0.x, ha.y, B00);
            A01 = fmaf(w0.y, ha.x, A01);  B01 = fmaf(w0.y, ha.y, B01);
            A02 = fmaf(w0.z, ha.x, A02);  B02 = fmaf(w0.z, ha.y, B02);
            A03 = fmaf(w0.w, ha.x, A03);  B03 = fmaf(w0.w, ha.y, B03);
            A00 = fmaf(w1.x, hbq.x, A00); B00 = fmaf(w1.x, hbq.y, B00);
            A01 = fmaf(w1.y, hbq.x, A01); B01 = fmaf(w1.y, hbq.y, B01);
            A02 = fmaf(w1.z, hbq.x, A02); B02 = fmaf(w1.z, hbq.y, B02);
            A03 = fmaf(w1.w, hbq.x, A03); B03 = fmaf(w1.w, hbq.y, B03);
        }
        {
            ulonglong2* pp = (ulonglong2*)(part + (size_t)q * DH + 4 * c);
            ulonglong2 s0; s0.x = pack2(A00, B00); s0.y = pack2(A01, B01);
            ulonglong2 s1; s1.x = pack2(A02, B02); s1.y = pack2(A03, B03);
            pp[0] = s0; pp[1] = s1;
        }
        __syncthreads();
        float hb0 = zp0, hb1 = zp1;
#pragma unroll
        for (int qq = 0; qq < 4; qq++) {
            float2 f = unpack2(part[(size_t)qq * DH + tid]);
            hb0 += f.x; hb1 += f.y;
        }

        // ---------- LN#1 (both batches) ----------
        float s00 = wred(hb0), s01 = wred(hb0 * hb0);
        float s10 = wred(hb1), s11 = wred(hb1 * hb1);
        if (l == 0) {
            red[0 * 12 + w] = s00; red[1 * 12 + w] = s01;
            red[2 * 12 + w] = s10; red[3 * 12 + w] = s11;
        }
        __syncthreads();
        float Shb0 = 0.f, Shb20 = 0.f, Shb1 = 0.f, Shb21 = 0.f;
        {
            const float4* r = (const float4*)red;
#pragma unroll
            for (int i = 0; i < 3; i++) {
                float4 x0 = r[i], x1 = r[3 + i], x2 = r[6 + i], x3 = r[9 + i];
                Shb0  += (x0.x + x0.y) + (x0.z + x0.w);
                Shb20 += (x1.x + x1.y) + (x1.z + x1.w);
                Shb1  += (x2.x + x2.y) + (x2.z + x2.w);
                Shb21 += (x3.x + x3.y) + (x3.z + x3.w);
            }
        }
        float mn0 = Shb0 * (1.f / DH);
        float rs0 = rsqrtf(Shb20 * (1.f / DH) - mn0 * mn0 + LN_EPS);
        hc0 = fmaxf((hb0 - mn0) * rs0 * gj + bj, 0.f);
        float mn1 = Shb1 * (1.f / DH);
        float rs1 = rsqrtf(Shb21 * (1.f / DH) - mn1 * mn1 + LN_EPS);
        hc1 = fmaxf((hb1 - mn1) * rs1 * gj + bj, 0.f);
        hsP[tid] = pack2(hc0, hc1);
        __syncthreads();

        const bool fin   = (t == TT - 1);
        const int  nh    = fin ? 47 : t;
        const int  dbase = fin ? 46 : (t - 1);

        // ---------- settling loop ----------
        for (int s = 0; s < 3; s++) {
            // dots[tau] (packed): warp-parallel over tau
            if (nh > 0) {
                ull hsv[12];
#pragma unroll
                for (int i = 0; i < 12; i++) hsv[i] = hsP[l + 32 * i];
                for (int tau = w; tau < nh; tau += NW) {
                    const ull* hr = histP + (size_t)tau * DH;
                    ull accP = 0ull;
#pragma unroll
                    for (int i = 0; i < 12; i++) accP = fma2(hr[l + 32 * i], hsv[i], accP);
                    float2 d = unpack2(accP);
                    float d0 = wred(d.x);
                    float d1 = wred(d.y);
                    if (l == 0) {
                        float lm = lampow[dbase - tau];
                        dotsP[tau] = pack2(d0 * lm, d1 * lm);
                    }
                }
            }
            __syncthreads();

            // Ah (packed): column scan of histP
            float Ah0 = 0.f, Ah1 = 0.f;
            {
                ull accA = 0ull;
#pragma unroll 4
                for (int tau = 0; tau < nh; tau++)
                    accA = fma2(dotsP[tau], histP[(size_t)tau * DH + tid], accA);
                float2 f = unpack2(accA);
                Ah0 = f.x; Ah1 = f.y;
            }

            // fused gate + LN reductions (5 sums x 2 batches)
            float r0 = wred(hc0 * Ah0), r1 = wred(hc0 * hc0), r2 = wred(Ah0 * Ah0);
            float r3 = wred(Ah0), r4 = wred(hb0 * Ah0);
            float u0 = wred(hc1 * Ah1), u1 = wred(hc1 * hc1), u2 = wred(Ah1 * Ah1);
            float u3 = wred(Ah1), u4 = wred(hb1 * Ah1);
            if (l == 0) {
                p5[0 * 12 + w] = r0; p5[1 * 12 + w] = r1; p5[2 * 12 + w] = r2;
                p5[3 * 12 + w] = r3; p5[4 * 12 + w] = r4;
                p5[5 * 12 + w] = u0; p5[6 * 12 + w] = u1; p5[7 * 12 + w] = u2;
                p5[8 * 12 + w] = u3; p5[9 * 12 + w] = u4;
            }
            __syncthreads();
            float S[10];
            {
                const float4* pv = (const float4*)p5;
#pragma unroll
                for (int rr = 0; rr < 10; rr++) {
                    float4 x = pv[rr * 3], y = pv[rr * 3 + 1], zq = pv[rr * 3 + 2];
                    S[rr] = ((x.x + x.y) + (x.z + x.w)) + ((y.x + y.y) + (y.z + y.w))
                          + ((zq.x + zq.y) + (zq.z + zq.w));
                }
            }
            // batch 0 scalars
            {
                float D = S[0], P = S[1], Q = S[2], SA = S[3], SX = S[4];
                float c1, ca;
                if (!fin) {
                    float R = D * rsqrtf(fmaxf(P, 1e-12f) * fmaxf(Q, 1e-12f));
                    R = fminf(fmaxf(R, 0.f), 1.f);
                    float a = 1.f - exp2f(kexp * log2f(1.f - R));
                    c1 = 1.f - a * a; ca = a;
                } else { c1 = 1.f; ca = 1.f; }
                float Sv  = c1 * Shb0 + ca * SA;
                float Sv2 = c1 * c1 * Shb20 + 2.f * c1 * ca * SX + ca * ca * Q;
                float mn  = Sv * (1.f / DH);
                float rs  = rsqrtf(Sv2 * (1.f / DH) - mn * mn + LN_EPS);
                hc0 = fmaxf((c1 * hb0 + ca * Ah0 - mn) * rs * gj + bj, 0.f);
            }
            // batch 1 scalars
            {
                float D = S[5], P = S[6], Q = S[7], SA = S[8], SX = S[9];
                float c1, ca;
                if (!fin) {
                    float R = D * rsqrtf(fmaxf(P, 1e-12f) * fmaxf(Q, 1e-12f));
                    R = fminf(fmaxf(R, 0.f), 1.f);
                    float a = 1.f - exp2f(kexp * log2f(1.f - R));
                    c1 = 1.f - a * a; ca = a;
                } else { c1 = 1.f; ca = 1.f; }
                float Sv  = c1 * Shb1 + ca * SA;
                float Sv2 = c1 * c1 * Shb21 + 2.f * c1 * ca * SX + ca * ca * Q;
                float mn  = Sv * (1.f / DH);
                float rs  = rsqrtf(Sv2 * (1.f / DH) - mn * mn + LN_EPS);
                hc1 = fmaxf((c1 * hb1 + ca * Ah1 - mn) * rs * gj + bj, 0.f);
            }
            hsP[tid] = pack2(hc0, hc1);
            __syncthreads();
        }
        if (!fin) histP[(size_t)t * DH + tid] = pack2(hc0, hc1);
        // next read of histP is after >=2 barriers in step t+1 — safe
    }
    out[(size_t)b0 * DH + tid] = hc0;
    out[(size_t)b1 * DH + tid] = hc1;
}

// ---------------- launch ----------------
extern "C" void kernel_launch(void* const* d_in, const int* in_sizes, int n_in,
                              void* d_out, int out_size) {
    const float* z     = (const float*)d_in[0];  // [48,96,192]
    const float* Wh    = (const float*)d_in[1];  // [384,384]
    const float* Wg    = (const float*)d_in[2];  // [384,192]
    const float* bh    = (const float*)d_in[3];  // [384]
    const float* lng   = (const float*)d_in[4];  // [384]
    const float* lnb   = (const float*)d_in[5];  // [384]
    const float* alpha = (const float*)d_in[6];  // [1]
    float* out = (float*)d_out;                  // [96,384]

    static int configured = 0;
    if (!configured) {
        cudaFuncSetAttribute(rnn_kernel, cudaFuncAttributeMaxDynamicSharedMemorySize, SM_BYTES);
        configured = 1;
    }

    transpose_k<<<dim3(12, 12), dim3(32, 8)>>>(Wh, DH, DH, 0);  // -> WT_g
    transpose_k<<<dim3(6, 12), dim3(32, 8)>>>(Wg, DH, DG, 1);   // -> WGT_g
    zp_kernel<<<TT * 6, NTH>>>(z, bh);
    rnn_kernel<<<BB / 2, NTH, SM_BYTES>>>(lng, lnb, alpha, out);
}

// round 8
// speedup vs baseline: 1.4234x; 1.4234x over previous
#include <cuda_runtime.h>
#include <cuda_bf16.h>
#include <cstdint>

#define DH 384
#define DG 192
#define TT 48
#define BB 96
#define NTHP 384        // prep kernels
#define NTH 768         // main kernel
#define LAM 0.9f
#define ETA 0.5f
#define LN_EPS 1e-5f

typedef unsigned long long ull;

// ---------------- device scratch (allocation-free rule) ----------------
__device__ float WT_g[DH * DH];              // W_h transposed: WT[j*DH + o] = W_h[o*DH + j]
__device__ float WGT_g[DG * DH];             // W_g transposed
__device__ float ZP_g[(size_t)TT * BB * DH]; // z @ W_g^T + b_h

// ---------------- helpers ----------------
__device__ __forceinline__ float wred(float v) {
#pragma unroll
    for (int o = 16; o; o >>= 1) v += __shfl_xor_sync(0xffffffffu, v, o);
    return v;
}
__device__ __forceinline__ ull fma2(ull a, ull b, ull c) {
    ull d;
    asm("fma.rn.f32x2 %0, %1, %2, %3;" : "=l"(d) : "l"(a), "l"(b), "l"(c));
    return d;
}
__device__ __forceinline__ ull splat2(float x) {
    ull d;
    asm("mov.b64 %0, {%1, %1};" : "=l"(d) : "f"(x));
    return d;
}
__device__ __forceinline__ float2 unpack2(ull v) {
    float lo, hi;
    asm("mov.b64 {%0, %1}, %2;" : "=f"(lo), "=f"(hi) : "l"(v));
    return make_float2(lo, hi);
}

// ---------------- transpose prep ----------------
__global__ void transpose_k(const float* __restrict__ src, int rows, int cols, int which) {
    __shared__ float tile[32][33];
    float* dst = (which == 0) ? WT_g : WGT_g;
    int c0 = blockIdx.x * 32, r0 = blockIdx.y * 32;
    int tx = threadIdx.x, ty = threadIdx.y;
#pragma unroll
    for (int k = 0; k < 4; k++)
        tile[ty + 8 * k][tx] = src[(size_t)(r0 + ty + 8 * k) * cols + c0 + tx];
    __syncthreads();
#pragma unroll
    for (int k = 0; k < 4; k++)
        dst[(size_t)(c0 + ty + 8 * k) * rows + r0 + tx] = tile[tx][ty + 8 * k];
}

// ---------------- z-projection prep (f32x2) ----------------
__global__ void zp_kernel(const float* __restrict__ z, const float* __restrict__ bh) {
    __shared__ float zt[DG * 18];
    int t = blockIdx.x / 6, bc = blockIdx.x % 6;
    int j = threadIdx.x;
    const float* zsrc = z + ((size_t)t * BB + bc * 16) * DG;
    for (int idx = j; idx < 16 * DG; idx += NTHP) {
        int m = idx / DG, i = idx % DG;
        zt[i * 18 + m] = zsrc[idx];
    }
    __syncthreads();
    ull acc[8];
    ull b2 = splat2(bh[j]);
#pragma unroll
    for (int p = 0; p < 8; p++) acc[p] = b2;
    for (int i = 0; i < DG; i++) {
        ull ws = splat2(WGT_g[(size_t)i * DH + j]);
        const ull* z2 = (const ull*)(zt + i * 18);
#pragma unroll
        for (int p = 0; p < 8; p++) acc[p] = fma2(ws, z2[p], acc[p]);
    }
    float* dst = ZP_g + ((size_t)t * BB + bc * 16) * DH + j;
#pragma unroll
    for (int p = 0; p < 8; p++) {
        float2 f = unpack2(acc[p]);
        dst[(size_t)(2 * p + 0) * DH] = f.x;
        dst[(size_t)(2 * p + 1) * DH] = f.y;
    }
}

// ---------------- main recurrence: one CTA per batch, 24 warps ----------------
// dyn smem floats: hist 47*384 | hs_lin 384 | part 8*384 | dots 48 | lampow 48 | red 24 | p5 60
#define SM_FLOATS (47 * DH + DH + 8 * DH + 48 + 48 + 24 + 60)
#define SM_BYTES (SM_FLOATS * 4)

__global__ void __launch_bounds__(NTH, 1)
rnn_kernel(const float* __restrict__ lng, const float* __restrict__ lnb,
           const float* __restrict__ alpha, float* __restrict__ out) {
    extern __shared__ __align__(16) float sm[];
    float* hist   = sm;                 // 47*384
    float* hs_lin = hist + 47 * DH;     // 384
    float* part   = hs_lin + DH;        // 8*384
    float* dots_s = part + 8 * DH;      // 48
    float* lampow = dots_s + 48;        // 48
    float* red    = lampow + 48;        // 2 x 12
    float* p5     = red + 24;           // 5 x 12

    const int b   = blockIdx.x;
    const int tid = threadIdx.x;
    const int w   = tid >> 5, l = tid & 31;
    const int q   = tid / 96, c = tid % 96;       // gemv mapping (8 x 96)
    const bool lower = (tid < DH);

    float alf = alpha[0];
    float kexp = (alf >= 0.f) ? (1.f + log1pf(expf(alf)))
                              : (1.f / (1.f + log1pf(expf(-alf))));
    float gj = 0.f, bj = 0.f;
    if (lower) { gj = lng[tid]; bj = lnb[tid]; }

    if (tid < 48) lampow[tid] = ETA * powf(LAM, (float)tid);
    if (lower) hs_lin[tid] = 0.f;
    __syncthreads();

    const float4* WT4 = (const float4*)WT_g;
    const float4* hs4 = (const float4*)hs_lin;
    const float4* wbase = WT4 + (size_t)(q * 48) * 96 + c;
    float hcur = 0.f;

    for (int t = 0; t < TT; t++) {
        // ---------- gemv: hb = W_h @ hs + ZP[t][b], 8-way j split ----------
        float zp = lower ? ZP_g[((size_t)t * BB + b) * DH + tid] : 0.f;
        float a0 = 0.f, a1 = 0.f, a2 = 0.f, a3 = 0.f;
#pragma unroll 3
        for (int i = 0; i < 12; i++) {
            float4 hv = hs4[q * 12 + i];
            float4 w0 = wbase[(size_t)(4 * i + 0) * 96];
            float4 w1 = wbase[(size_t)(4 * i + 1) * 96];
            float4 w2 = wbase[(size_t)(4 * i + 2) * 96];
            float4 w3 = wbase[(size_t)(4 * i + 3) * 96];
            a0 = fmaf(hv.x, w0.x, fmaf(hv.y, w1.x, fmaf(hv.z, w2.x, fmaf(hv.w, w3.x, a0))));
            a1 = fmaf(hv.x, w0.y, fmaf(hv.y, w1.y, fmaf(hv.z, w2.y, fmaf(hv.w, w3.y, a1))));
            a2 = fmaf(hv.x, w0.z, fmaf(hv.y, w1.z, fmaf(hv.z, w2.z, fmaf(hv.w, w3.z, a2))));
            a3 = fmaf(hv.x, w0.w, fmaf(hv.y, w1.w, fmaf(hv.z, w2.w, fmaf(hv.w, w3.w, a3))));
        }
        {
            float4 st4; st4.x = a0; st4.y = a1; st4.z = a2; st4.w = a3;
            *(float4*)(part + (size_t)q * DH + 4 * c) = st4;
        }
        __syncthreads();

        float hb = zp;
        if (lower) {
#pragma unroll
            for (int qq = 0; qq < 8; qq++) hb += part[qq * DH + tid];
        }

        // ---------- LN#1 (lower 12 warps reduce) ----------
        if (w < 12) {
            float s0 = wred(hb);
            float s1 = wred(hb * hb);
            if (l == 0) { red[w] = s0; red[12 + w] = s1; }
        }
        __syncthreads();
        float Shb = 0.f, Shb2 = 0.f;
        {
            const float4* r0 = (const float4*)red;
#pragma unroll
            for (int i = 0; i < 3; i++) {
                float4 a = r0[i], bq = r0[3 + i];
                Shb  += (a.x + a.y) + (a.z + a.w);
                Shb2 += (bq.x + bq.y) + (bq.z + bq.w);
            }
        }
        float mean = Shb * (1.f / DH);
        float rstd = rsqrtf(Shb2 * (1.f / DH) - mean * mean + LN_EPS);
        hcur = fmaxf((hb - mean) * rstd * gj + bj, 0.f);
        if (lower) hs_lin[tid] = hcur;
        __syncthreads();

        const bool fin   = (t == TT - 1);
        const int  nh    = fin ? 47 : t;
        const int  dbase = fin ? 46 : (t - 1);

        // ---------- settling loop ----------
        for (int s = 0; s < 3; s++) {
            // dots[tau]: warp-parallel over tau (24 warps)
            if (nh > 0) {
                float hsv[12];
#pragma unroll
                for (int i = 0; i < 12; i++) hsv[i] = hs_lin[l + 32 * i];
                for (int tau = w; tau < nh; tau += 24) {
                    const float* hr = hist + (size_t)tau * DH;
                    float d = 0.f;
#pragma unroll
                    for (int i = 0; i < 12; i++) d = fmaf(hr[l + 32 * i], hsv[i], d);
                    d = wred(d);
                    if (l == 0) dots_s[tau] = d * lampow[dbase - tau];
                }
            }
            __syncthreads();

            // Ah + fused reductions (lower threads)
            float Ah = 0.f;
            if (lower) {
                float A0 = 0.f, A1 = 0.f, A2 = 0.f, A3 = 0.f;
                int tau = 0;
                for (; tau + 4 <= nh; tau += 4) {
                    A0 = fmaf(dots_s[tau + 0], hist[(size_t)(tau + 0) * DH + tid], A0);
                    A1 = fmaf(dots_s[tau + 1], hist[(size_t)(tau + 1) * DH + tid], A1);
                    A2 = fmaf(dots_s[tau + 2], hist[(size_t)(tau + 2) * DH + tid], A2);
                    A3 = fmaf(dots_s[tau + 3], hist[(size_t)(tau + 3) * DH + tid], A3);
                }
                for (; tau < nh; tau++)
                    A0 = fmaf(dots_s[tau], hist[(size_t)tau * DH + tid], A0);
                Ah = (A0 + A1) + (A2 + A3);

                if (w < 12) {
                    float r0 = wred(hcur * Ah);
                    float r1 = wred(hcur * hcur);
                    float r2 = wred(Ah * Ah);
                    float r3 = wred(Ah);
                    float r4 = wred(hb * Ah);
                    if (l == 0) {
                        p5[w] = r0; p5[12 + w] = r1; p5[24 + w] = r2;
                        p5[36 + w] = r3; p5[48 + w] = r4;
                    }
                }
            }
            __syncthreads();

            float S[5];
            {
                const float4* pv = (const float4*)p5;
#pragma unroll
                for (int v = 0; v < 5; v++) {
                    float4 x = pv[v * 3], y = pv[v * 3 + 1], zq = pv[v * 3 + 2];
                    S[v] = ((x.x + x.y) + (x.z + x.w)) + ((y.x + y.y) + (y.z + y.w))
                         + ((zq.x + zq.y) + (zq.z + zq.w));
                }
            }
            float D = S[0], P = S[1], Q = S[2], SA = S[3], SX = S[4];

            float c1, ca;
            if (!fin) {
                float R = D * rsqrtf(fmaxf(P, 1e-12f) * fmaxf(Q, 1e-12f));
                R = fminf(fmaxf(R, 0.f), 1.f);
                float a = 1.f - exp2f(kexp * log2f(1.f - R));
                c1 = 1.f - a * a; ca = a;
            } else { c1 = 1.f; ca = 1.f; }
            float Sv  = c1 * Shb + ca * SA;
            float Sv2 = c1 * c1 * Shb2 + 2.f * c1 * ca * SX + ca * ca * Q;
            float mn  = Sv * (1.f / DH);
            float rs  = rsqrtf(Sv2 * (1.f / DH) - mn * mn + LN_EPS);
            hcur = fmaxf((c1 * hb + ca * Ah - mn) * rs * gj + bj, 0.f);
            if (lower) hs_lin[tid] = hcur;
            __syncthreads();
        }

        if (!fin && lower) hist[(size_t)t * DH + tid] = hcur;
        // next hist read is after >=2 barriers in step t+1 — safe
    }
    if (lower) out[(size_t)b * DH + tid] = hcur;
}

// ---------------- launch ----------------
extern "C" void kernel_launch(void* const* d_in, const int* in_sizes, int n_in,
                              void* d_out, int out_size) {
    const float* z     = (const float*)d_in[0];  // [48,96,192]
    const float* Wh    = (const float*)d_in[1];  // [384,384]
    const float* Wg    = (const float*)d_in[2];  // [384,192]
    const float* bh    = (const float*)d_in[3];  // [384]
    const float* lng   = (const float*)d_in[4];  // [384]
    const float* lnb   = (const float*)d_in[5];  // [384]
    const float* alpha = (const float*)d_in[6];  // [1]
    float* out = (float*)d_out;                  // [96,384]

    static int configured = 0;
    if (!configured) {
        cudaFuncSetAttribute(rnn_kernel, cudaFuncAttributeMaxDynamicSharedMemorySize, SM_BYTES);
        configured = 1;
    }

    transpose_k<<<dim3(12, 12), dim3(32, 8)>>>(Wh, DH, DH, 0);  // -> WT_g
    transpose_k<<<dim3(6, 12), dim3(32, 8)>>>(Wg, DH, DG, 1);   // -> WGT_g
    zp_kernel<<<TT * 6, NTHP>>>(z, bh);
    rnn_kernel<<<BB, NTH, SM_BYTES>>>(lng, lnb, alpha, out);
}

// round 9
// speedup vs baseline: 2.2307x; 1.5672x over previous
#include <cuda_runtime.h>
#include <cuda_bf16.h>
#include <cstdint>

#define DH 384
#define DG 192
#define TT 48
#define BB 96
#define NTH 384
#define NW 12
#define LAM 0.9f
#define ETA 0.5f
#define LN_EPS 1e-5f

typedef unsigned long long ull;

// ---------------- device scratch (allocation-free rule) ----------------
__device__ float WT_g[DH * DH];              // W_h transposed: WT[j*DH + o] = W_h[o*DH + j]
__device__ float WGT_g[DG * DH];             // W_g transposed
__device__ float ZP_g[(size_t)TT * BB * DH]; // z @ W_g^T + b_h

// ---------------- helpers ----------------
__device__ __forceinline__ float wred(float v) {
#pragma unroll
    for (int o = 16; o; o >>= 1) v += __shfl_xor_sync(0xffffffffu, v, o);
    return v;
}
__device__ __forceinline__ ull fma2(ull a, ull b, ull c) {
    ull d;
    asm("fma.rn.f32x2 %0, %1, %2, %3;" : "=l"(d) : "l"(a), "l"(b), "l"(c));
    return d;
}
__device__ __forceinline__ ull pack2(float lo, float hi) {
    ull d;
    asm("mov.b64 %0, {%1, %2};" : "=l"(d) : "f"(lo), "f"(hi));
    return d;
}
__device__ __forceinline__ ull splat2(float x) {
    ull d;
    asm("mov.b64 %0, {%1, %1};" : "=l"(d) : "f"(x));
    return d;
}
__device__ __forceinline__ float2 unpack2(ull v) {
    float lo, hi;
    asm("mov.b64 {%0, %1}, %2;" : "=f"(lo), "=f"(hi) : "l"(v));
    return make_float2(lo, hi);
}

// ---------------- transpose prep ----------------
__global__ void transpose_k(const float* __restrict__ src, int rows, int cols, int which) {
    __shared__ float tile[32][33];
    float* dst = (which == 0) ? WT_g : WGT_g;
    int c0 = blockIdx.x * 32, r0 = blockIdx.y * 32;
    int tx = threadIdx.x, ty = threadIdx.y;
#pragma unroll
    for (int k = 0; k < 4; k++)
        tile[ty + 8 * k][tx] = src[(size_t)(r0 + ty + 8 * k) * cols + c0 + tx];
    __syncthreads();
#pragma unroll
    for (int k = 0; k < 4; k++)
        dst[(size_t)(c0 + ty + 8 * k) * rows + r0 + tx] = tile[tx][ty + 8 * k];
}

// ---------------- z-projection prep (f32x2) ----------------
__global__ void zp_kernel(const float* __restrict__ z, const float* __restrict__ bh) {
    __shared__ float zt[DG * 18];
    int t = blockIdx.x / 6, bc = blockIdx.x % 6;
    int j = threadIdx.x;
    const float* zsrc = z + ((size_t)t * BB + bc * 16) * DG;
    for (int idx = j; idx < 16 * DG; idx += NTH) {
        int m = idx / DG, i = idx % DG;
        zt[i * 18 + m] = zsrc[idx];
    }
    __syncthreads();
    ull acc[8];
    ull b2 = splat2(bh[j]);
#pragma unroll
    for (int p = 0; p < 8; p++) acc[p] = b2;
    for (int i = 0; i < DG; i++) {
        ull ws = splat2(WGT_g[(size_t)i * DH + j]);
        const ull* z2 = (const ull*)(zt + i * 18);
#pragma unroll
        for (int p = 0; p < 8; p++) acc[p] = fma2(ws, z2[p], acc[p]);
    }
    float* dst = ZP_g + ((size_t)t * BB + bc * 16) * DH + j;
#pragma unroll
    for (int p = 0; p < 8; p++) {
        float2 f = unpack2(acc[p]);
        dst[(size_t)(2 * p + 0) * DH] = f.x;
        dst[(size_t)(2 * p + 1) * DH] = f.y;
    }
}

// ---------------- main recurrence: one CTA per batch, sparse gemv ----------------
// dyn smem floats:
//   hist 47*384 | hsA 384 | hsB 384 | part 4*384 | sidxval 384*2 |
//   dots 48 | lampow 48 | red 24 | p5 60 | wcnt 12
#define SM_FLOATS (47 * DH + DH + DH + 4 * DH + 2 * DH + 48 + 48 + 24 + 60 + 12)
#define SM_BYTES (SM_FLOATS * 4)

__global__ void __launch_bounds__(NTH, 1)
rnn_kernel(const float* __restrict__ lng, const float* __restrict__ lnb,
           const float* __restrict__ alpha, float* __restrict__ out) {
    extern __shared__ __align__(16) float sm[];
    float*  hist    = sm;                    // 47*384
    float*  hsA     = hist + 47 * DH;        // 384
    float*  hsB     = hsA + DH;              // 384
    float*  part    = hsB + DH;              // 4*384
    float2* sidxval = (float2*)(part + 4 * DH);  // 384 pairs (idx-as-float, val)
    float*  dots_s  = part + 4 * DH + 2 * DH;    // 48
    float*  lampow  = dots_s + 48;           // 48
    float*  red     = lampow + 48;           // 2 x 12
    float*  p5      = red + 24;              // 5 x 12
    int*    wcnt    = (int*)(p5 + 60);       // 12

    const int b   = blockIdx.x;
    const int tid = threadIdx.x;
    const int w   = tid >> 5, l = tid & 31;
    const int q   = tid / 96, c = tid % 96;
    const unsigned lmask_lt = (l == 0) ? 0u : (0xffffffffu >> (32 - l));

    float alf = alpha[0];
    float kexp = (alf >= 0.f) ? (1.f + log1pf(expf(alf)))
                              : (1.f / (1.f + log1pf(expf(-alf))));
    float gj = lng[tid], bj = lnb[tid];

    if (tid < 48) lampow[tid] = ETA * powf(LAM, (float)tid);

    float hreg[47];
#pragma unroll
    for (int i = 0; i < 47; i++) hreg[i] = 0.f;
    __syncthreads();

    const float4* WT4 = (const float4*)WT_g;
    float hcur = 0.f;
    int nnz = 0;                 // nonzero count of current hs (0 at t=0: h0=0)

    for (int t = 0; t < TT; t++) {
        // ---------- sparse gemv: hb = W_h @ hs + ZP[t][b] ----------
        float zp = ZP_g[((size_t)t * BB + b) * DH + tid];
        ull aXY = 0ull, aZW = 0ull;
        {
            int i0 = (nnz * q) >> 2;
            int i1 = (nnz * (q + 1)) >> 2;
            int i = i0;
            for (; i + 2 <= i1; i += 2) {
                float2 iv0 = sidxval[i];
                float2 iv1 = sidxval[i + 1];
                float4 w0 = WT4[(size_t)__float_as_int(iv0.x) * 96 + c];
                float4 w1 = WT4[(size_t)__float_as_int(iv1.x) * 96 + c];
                ull v0 = splat2(iv0.y), v1 = splat2(iv1.y);
                aXY = fma2(v0, pack2(w0.x, w0.y), aXY);
                aZW = fma2(v0, pack2(w0.z, w0.w), aZW);
                aXY = fma2(v1, pack2(w1.x, w1.y), aXY);
                aZW = fma2(v1, pack2(w1.z, w1.w), aZW);
            }
            if (i < i1) {
                float2 iv0 = sidxval[i];
                float4 w0 = WT4[(size_t)__float_as_int(iv0.x) * 96 + c];
                ull v0 = splat2(iv0.y);
                aXY = fma2(v0, pack2(w0.x, w0.y), aXY);
                aZW = fma2(v0, pack2(w0.z, w0.w), aZW);
            }
        }
        {
            ulonglong2 st2; st2.x = aXY; st2.y = aZW;
            ((ulonglong2*)part)[tid] = st2;   // part[q*384 + 4c .. +3]
        }
        __syncthreads();
        float hb = zp;
#pragma unroll
        for (int qq = 0; qq < 4; qq++) hb += part[qq * DH + tid];

        // ---------- LN#1 ----------
        float s0 = wred(hb);
        float s1 = wred(hb * hb);
        if (l == 0) { red[w] = s0; red[12 + w] = s1; }
        __syncthreads();
        float Shb = 0.f, Shb2 = 0.f;
        {
            const float4* r0 = (const float4*)red;
#pragma unroll
            for (int i = 0; i < 3; i++) {
                float4 a = r0[i], bq = r0[3 + i];
                Shb  += (a.x + a.y) + (a.z + a.w);
                Shb2 += (bq.x + bq.y) + (bq.z + bq.w);
            }
        }
        float mean = Shb * (1.f / DH);
        float rstd = rsqrtf(Shb2 * (1.f / DH) - mean * mean + LN_EPS);
        hcur = fmaxf((hb - mean) * rstd * gj + bj, 0.f);
        hsA[tid] = hcur;
        __syncthreads();

        const bool fin   = (t == TT - 1);
        const int  nh    = fin ? 47 : t;
        const int  dbase = fin ? 46 : (t - 1);

        // ---------- settling loop (double-buffered hs) ----------
        const float* hsbuf[2] = { hsA, hsB };
        int cur = 0;
        for (int s = 0; s < 3; s++) {
            // dots[tau]: warp-parallel over tau
            if (nh > 0) {
                const float* hsrd = hsbuf[cur];
                float hsv[12];
#pragma unroll
                for (int i = 0; i < 12; i++) hsv[i] = hsrd[l + 32 * i];
                for (int tau = w; tau < nh; tau += NW) {
                    const float* hr = hist + (size_t)tau * DH;
                    float d = 0.f;
#pragma unroll
                    for (int i = 0; i < 12; i++) d = fmaf(hr[l + 32 * i], hsv[i], d);
                    d = wred(d);
                    if (l == 0) dots_s[tau] = d * lampow[dbase - tau];
                }
            }
            __syncthreads();

            // Ah[tid] = sum_tau dots[tau]*hreg[tau]
            float dv[48];
            {
                const float4* d4 = (const float4*)dots_s;
#pragma unroll
                for (int i = 0; i < 12; i++) {
                    float4 v = d4[i];
                    dv[4 * i] = v.x; dv[4 * i + 1] = v.y; dv[4 * i + 2] = v.z; dv[4 * i + 3] = v.w;
                }
            }
            float A0 = 0.f, A1 = 0.f, A2 = 0.f, A3 = 0.f;
#pragma unroll
            for (int tau = 0; tau < 47; tau += 4) {
                A0 = fmaf(dv[tau], hreg[tau], A0);
                if (tau + 1 < 47) A1 = fmaf(dv[tau + 1], hreg[tau + 1], A1);
                if (tau + 2 < 47) A2 = fmaf(dv[tau + 2], hreg[tau + 2], A2);
                if (tau + 3 < 47) A3 = fmaf(dv[tau + 3], hreg[tau + 3], A3);
            }
            float Ah = (A0 + A1) + (A2 + A3);

            // fused gate + LN reduction
            float r0 = wred(hcur * Ah);
            float r1 = wred(hcur * hcur);
            float r2 = wred(Ah * Ah);
            float r3 = wred(Ah);
            float r4 = wred(hb * Ah);
            if (l == 0) {
                p5[w] = r0; p5[12 + w] = r1; p5[24 + w] = r2; p5[36 + w] = r3; p5[48 + w] = r4;
            }
            __syncthreads();
            float S[5];
            {
                const float4* pv = (const float4*)p5;
#pragma unroll
                for (int v = 0; v < 5; v++) {
                    float4 x = pv[v * 3], y = pv[v * 3 + 1], zq = pv[v * 3 + 2];
                    S[v] = ((x.x + x.y) + (x.z + x.w)) + ((y.x + y.y) + (y.z + y.w))
                         + ((zq.x + zq.y) + (zq.z + zq.w));
                }
            }
            float D = S[0], P = S[1], Q = S[2], SA = S[3], SX = S[4];

            float c1, ca;
            if (!fin) {
                float R = D * rsqrtf(fmaxf(P, 1e-12f) * fmaxf(Q, 1e-12f));
                R = fminf(fmaxf(R, 0.f), 1.f);
                float a = 1.f - exp2f(kexp * log2f(1.f - R));
                c1 = 1.f - a * a; ca = a;
            } else { c1 = 1.f; ca = 1.f; }
            float Sv  = c1 * Shb + ca * SA;
            float Sv2 = c1 * c1 * Shb2 + 2.f * c1 * ca * SX + ca * ca * Q;
            float mn  = Sv * (1.f / DH);
            float rs  = rsqrtf(Sv2 * (1.f / DH) - mn * mn + LN_EPS);
            hcur = fmaxf((c1 * hb + ca * Ah - mn) * rs * gj + bj, 0.f);

            ((float*)hsbuf[cur ^ 1])[tid] = hcur;
            cur ^= 1;
            __syncthreads();
        }

        if (!fin) {
            hist[(size_t)t * DH + tid] = hcur;
#pragma unroll
            for (int i = 0; i < 47; i++)
                if (i == t) hreg[i] = hcur;

            // ---------- compact nonzeros of hcur for next step's sparse gemv ----------
            unsigned mask = __ballot_sync(0xffffffffu, hcur != 0.f);
            if (l == 0) wcnt[w] = __popc(mask);
            __syncthreads();
            int base = 0, tot = 0;
#pragma unroll
            for (int i = 0; i < NW; i++) {
                int cv = wcnt[i];
                if (i < w) base += cv;
                tot += cv;
            }
            nnz = tot;
            if (hcur != 0.f) {
                int pos = base + __popc(mask & lmask_lt);
                sidxval[pos] = make_float2(__int_as_float(tid), hcur);
            }
            __syncthreads();
        }
    }
    out[(size_t)b * DH + tid] = hcur;
}

// ---------------- launch ----------------
extern "C" void kernel_launch(void* const* d_in, const int* in_sizes, int n_in,
                              void* d_out, int out_size) {
    const float* z     = (const float*)d_in[0];  // [48,96,192]
    const float* Wh    = (const float*)d_in[1];  // [384,384]
    const float* Wg    = (const float*)d_in[2];  // [384,192]
    const float* bh    = (const float*)d_in[3];  // [384]
    const float* lng   = (const float*)d_in[4];  // [384]
    const float* lnb   = (const float*)d_in[5];  // [384]
    const float* alpha = (const float*)d_in[6];  // [1]
    float* out = (float*)d_out;                  // [96,384]

    static int configured = 0;
    if (!configured) {
        cudaFuncSetAttribute(rnn_kernel, cudaFuncAttributeMaxDynamicSharedMemorySize, SM_BYTES);
        configured = 1;
    }

    transpose_k<<<dim3(12, 12), dim3(32, 8)>>>(Wh, DH, DH, 0);  // -> WT_g
    transpose_k<<<dim3(6, 12), dim3(32, 8)>>>(Wg, DH, DG, 1);   // -> WGT_g
    zp_kernel<<<TT * 6, NTH>>>(z, bh);
    rnn_kernel<<<BB, NTH, SM_BYTES>>>(lng, lnb, alpha, out);
}